// round 1
// baseline (speedup 1.0000x reference)
#include <cuda_runtime.h>

#define H_FEATS 512
#define N_NODES 50000
#define N_EDGES 500000

// Scratch: per-node projections (fp32 for accuracy) + repacked weight
__device__ float g_A[(size_t)N_NODES * H_FEATS];   // h @ W1a + b1
__device__ float g_B[(size_t)N_NODES * H_FEATS];   // h @ W1b
__device__ float g_Wt[(size_t)H_FEATS * 2 * H_FEATS]; // [512][1024]: cols 0..511 = W1a, 512..1023 = W1b

// ---------------------------------------------------------------------------
// Repack W1 (1024x512 row-major) into Wt (512x1024): Wt[k][j] = W1a[k][j] for
// j<512, W1b[k][j-512] for j>=512.
// ---------------------------------------------------------------------------
__global__ void repack_w1(const float* __restrict__ W1) {
    int idx = blockIdx.x * blockDim.x + threadIdx.x;     // over 512*1024
    if (idx >= H_FEATS * 2 * H_FEATS) return;
    int k = idx >> 10;          // 0..511
    int j = idx & 1023;         // 0..1023
    float v = (j < H_FEATS) ? W1[k * H_FEATS + j]
                            : W1[(k + H_FEATS) * H_FEATS + (j - H_FEATS)];
    g_Wt[(size_t)k * 1024 + j] = v;
}

// ---------------------------------------------------------------------------
// Node GEMM: C[n][j] = sum_k h[n][k] * Wt[k][j], n<50000, j<1024.
// Epilogue: j<512 -> g_A[n][j] = C + b1[j];  j>=512 -> g_B[n][j-512] = C.
// 128x128 tile, BK=8, 256 threads, 8x8 per-thread microtile.
// ---------------------------------------------------------------------------
#define BM 128
#define BN 128
#define BK 8
#define TM 8
#define TN 8

__global__ __launch_bounds__(256) void node_gemm(const float* __restrict__ h,
                                                 const float* __restrict__ b1) {
    __shared__ float As[BK][BM];
    __shared__ float Bs[BK][BN];

    const int bx = blockIdx.x;          // N tiles: 1024/128 = 8
    const int by = blockIdx.y;          // M tiles: ceil(50000/128) = 391
    const int tid = threadIdx.x;
    const int tx = tid & 15;            // 16 thread cols
    const int ty = tid >> 4;            // 16 thread rows

    // Global-load assignments (float4 each)
    const int aRow = tid >> 1;               // 128 rows, 2 float4 loaders per row
    const int aCol = (tid & 1) * 4;          // 0 or 4 within BK=8
    const int bRow = tid >> 5;               // 8 rows of Bs
    const int bCol = (tid & 31) * 4;         // 128 cols, float4

    const int mBase = by * BM;
    const int mMax  = N_NODES - mBase;       // rows valid in this tile (may be < BM)

    const float* hBase = h + (size_t)mBase * H_FEATS;
    const float* wBase = g_Wt + (size_t)bx * BN;

    float acc[TM][TN];
    #pragma unroll
    for (int i = 0; i < TM; i++)
        #pragma unroll
        for (int j = 0; j < TN; j++) acc[i][j] = 0.f;

    for (int k0 = 0; k0 < H_FEATS; k0 += BK) {
        // Load A tile (transposed into As[k][m]) — guard tail rows
        float4 av = make_float4(0.f, 0.f, 0.f, 0.f);
        if (aRow < mMax)
            av = *(const float4*)(hBase + (size_t)aRow * H_FEATS + k0 + aCol);
        As[aCol + 0][aRow] = av.x;
        As[aCol + 1][aRow] = av.y;
        As[aCol + 2][aRow] = av.z;
        As[aCol + 3][aRow] = av.w;

        // Load B tile
        float4 bv = *(const float4*)(wBase + (size_t)(k0 + bRow) * 1024 + bCol);
        *(float4*)&Bs[bRow][bCol] = bv;

        __syncthreads();

        #pragma unroll
        for (int k = 0; k < BK; k++) {
            float ar[TM], br[TN];
            #pragma unroll
            for (int i = 0; i < TM; i++) ar[i] = As[k][ty * TM + i];
            #pragma unroll
            for (int j = 0; j < TN; j++) br[j] = Bs[k][tx * TN + j];
            #pragma unroll
            for (int i = 0; i < TM; i++)
                #pragma unroll
                for (int j = 0; j < TN; j++)
                    acc[i][j] = fmaf(ar[i], br[j], acc[i][j]);
        }
        __syncthreads();
    }

    // Epilogue: whole block is in one half (BN=128 divides 512 cleanly)
    const bool isA = (bx < 4);
    #pragma unroll
    for (int i = 0; i < TM; i++) {
        int row = mBase + ty * TM + i;
        if (row >= N_NODES) continue;
        #pragma unroll
        for (int j = 0; j < TN; j += 4) {
            int col = bx * BN + tx * TN + j;      // global col 0..1023
            float4 v;
            v.x = acc[i][j + 0];
            v.y = acc[i][j + 1];
            v.z = acc[i][j + 2];
            v.w = acc[i][j + 3];
            if (isA) {
                int c = col;                      // 0..511
                v.x += b1[c + 0]; v.y += b1[c + 1];
                v.z += b1[c + 2]; v.w += b1[c + 3];
                *(float4*)(g_A + (size_t)row * H_FEATS + c) = v;
            } else {
                int c = col - H_FEATS;            // 0..511
                *(float4*)(g_B + (size_t)row * H_FEATS + c) = v;
            }
        }
    }
}

// ---------------------------------------------------------------------------
// Edge kernel: one warp per edge.
// score[e] = sum_j relu(A[src[e]][j] + B[dst[e]][j]) * W2[j]  + b2
// (b1 already folded into A.)
// ---------------------------------------------------------------------------
__global__ __launch_bounds__(256) void edge_score(const int* __restrict__ src,
                                                  const int* __restrict__ dst,
                                                  const float* __restrict__ W2,
                                                  const float* __restrict__ b2,
                                                  float* __restrict__ out) {
    const int warpsPerBlock = blockDim.x >> 5;
    const int e = blockIdx.x * warpsPerBlock + (threadIdx.x >> 5);
    if (e >= N_EDGES) return;
    const int lane = threadIdx.x & 31;

    const int s = src[e];
    const int d = dst[e];

    const float4* a = (const float4*)(g_A + (size_t)s * H_FEATS);
    const float4* b = (const float4*)(g_B + (size_t)d * H_FEATS);
    const float4* w = (const float4*)W2;

    float sum = 0.f;
    #pragma unroll
    for (int c = 0; c < (H_FEATS / 4) / 32; c++) {   // 4 iterations
        int idx = c * 32 + lane;
        float4 av = a[idx];
        float4 bv = b[idx];
        float4 wv = w[idx];
        sum = fmaf(fmaxf(av.x + bv.x, 0.f), wv.x, sum);
        sum = fmaf(fmaxf(av.y + bv.y, 0.f), wv.y, sum);
        sum = fmaf(fmaxf(av.z + bv.z, 0.f), wv.z, sum);
        sum = fmaf(fmaxf(av.w + bv.w, 0.f), wv.w, sum);
    }

    // warp reduce
    #pragma unroll
    for (int off = 16; off > 0; off >>= 1)
        sum += __shfl_xor_sync(0xFFFFFFFFu, sum, off);

    if (lane == 0) out[e] = sum + b2[0];
}

// ---------------------------------------------------------------------------
// Launch
// ---------------------------------------------------------------------------
extern "C" void kernel_launch(void* const* d_in, const int* in_sizes, int n_in,
                              void* d_out, int out_size) {
    const float* h   = (const float*)d_in[0];
    const int*   src = (const int*)  d_in[1];
    const int*   dst = (const int*)  d_in[2];
    const float* W1  = (const float*)d_in[3];
    const float* b1  = (const float*)d_in[4];
    const float* W2  = (const float*)d_in[5];
    const float* b2  = (const float*)d_in[6];
    float* out = (float*)d_out;

    // 1) repack W1 -> Wt
    {
        int total = H_FEATS * 2 * H_FEATS;
        repack_w1<<<(total + 255) / 256, 256>>>(W1);
    }

    // 2) node GEMM: A = h@W1a + b1, B = h@W1b
    {
        dim3 grid(2 * H_FEATS / BN, (N_NODES + BM - 1) / BM);  // (8, 391)
        node_gemm<<<grid, 256>>>(h, b1);
    }

    // 3) edge scoring: one warp per edge
    {
        int warpsPerBlock = 8;  // 256 threads
        int blocks = (N_EDGES + warpsPerBlock - 1) / warpsPerBlock;
        edge_score<<<blocks, 256>>>(src, dst, W2, b2, out);
    }
}

// round 5
// speedup vs baseline: 2.3271x; 2.3271x over previous
#include <cuda_runtime.h>
#include <cuda_bf16.h>

#define H_FEATS 512
#define N_NODES 50000
#define N_EDGES 500000

// ---------------------------------------------------------------------------
// Device scratch (static — no allocation allowed)
// ---------------------------------------------------------------------------
__device__ float g_A[(size_t)N_NODES * H_FEATS];            // h @ W1a + b1
__device__ float g_B[(size_t)N_NODES * H_FEATS];            // h @ W1b
__device__ __nv_bfloat16 g_hh[(size_t)N_NODES * H_FEATS];   // bf16 hi of h
__device__ __nv_bfloat16 g_hl[(size_t)N_NODES * H_FEATS];   // bf16 lo of h
__device__ __nv_bfloat16 g_Wbh[(size_t)1024 * H_FEATS];     // B operand hi: [j][k], k-major
__device__ __nv_bfloat16 g_Wbl[(size_t)1024 * H_FEATS];     // B operand lo

// ---------------------------------------------------------------------------
// Helpers
// ---------------------------------------------------------------------------
__device__ __forceinline__ unsigned smem_u32(const void* p) {
    unsigned a;
    asm("{ .reg .u64 t; cvta.to.shared.u64 t, %1; cvt.u32.u64 %0, t; }" : "=r"(a) : "l"(p));
    return a;
}
__device__ __forceinline__ void cp16(unsigned dst, const void* src, unsigned vsize) {
    asm volatile("cp.async.cg.shared.global [%0], [%1], 16, %2;"
                 :: "r"(dst), "l"(src), "r"(vsize) : "memory");
}
#define SW128(x) ((x) ^ (((x) >> 3) & 0x70))

__device__ __forceinline__ void ldsm4(unsigned& r0, unsigned& r1, unsigned& r2, unsigned& r3,
                                      unsigned addr) {
    asm volatile("ldmatrix.sync.aligned.m8n8.x4.shared.b16 {%0,%1,%2,%3}, [%4];"
                 : "=r"(r0), "=r"(r1), "=r"(r2), "=r"(r3) : "r"(addr));
}
__device__ __forceinline__ void mma16816(float* c, const unsigned* a, const unsigned* b) {
    asm volatile(
        "mma.sync.aligned.m16n8k16.row.col.f32.bf16.bf16.f32 "
        "{%0,%1,%2,%3}, {%4,%5,%6,%7}, {%8,%9}, {%0,%1,%2,%3};"
        : "+f"(c[0]), "+f"(c[1]), "+f"(c[2]), "+f"(c[3])
        : "r"(a[0]), "r"(a[1]), "r"(a[2]), "r"(a[3]), "r"(b[0]), "r"(b[1]));
}

// ---------------------------------------------------------------------------
// Convert h -> bf16 hi/lo split
// ---------------------------------------------------------------------------
__global__ void convert_h(const float* __restrict__ h) {
    int i = blockIdx.x * blockDim.x + threadIdx.x;
    const int total = N_NODES * H_FEATS / 4;
    if (i >= total) return;
    float4 v = ((const float4*)h)[i];
    __nv_bfloat16 h0 = __float2bfloat16(v.x), h1 = __float2bfloat16(v.y);
    __nv_bfloat16 h2 = __float2bfloat16(v.z), h3 = __float2bfloat16(v.w);
    __nv_bfloat16 l0 = __float2bfloat16(v.x - __bfloat162float(h0));
    __nv_bfloat16 l1 = __float2bfloat16(v.y - __bfloat162float(h1));
    __nv_bfloat16 l2 = __float2bfloat16(v.z - __bfloat162float(h2));
    __nv_bfloat16 l3 = __float2bfloat16(v.w - __bfloat162float(h3));
    __nv_bfloat162* hh = (__nv_bfloat162*)g_hh;
    __nv_bfloat162* hl = (__nv_bfloat162*)g_hl;
    hh[2 * i]     = __nv_bfloat162(h0, h1);
    hh[2 * i + 1] = __nv_bfloat162(h2, h3);
    hl[2 * i]     = __nv_bfloat162(l0, l1);
    hl[2 * i + 1] = __nv_bfloat162(l2, l3);
}

// ---------------------------------------------------------------------------
// Repack W1 (1024x512 row-major) into [j=0..1023][k] k-major bf16 hi/lo:
//   j < 512:  B[j][k] = W1[k][j]        (W1a col j)
//   j >= 512: B[j][k] = W1[k+512][j-512]
// ---------------------------------------------------------------------------
__global__ void repack_w(const float* __restrict__ W1) {
    int idx = blockIdx.x * blockDim.x + threadIdx.x;
    const int total = 1024 * H_FEATS;
    if (idx >= total) return;
    int j = idx >> 9;
    int k = idx & 511;
    int r = (j < H_FEATS) ? k : (k + H_FEATS);
    float v = W1[(size_t)r * H_FEATS + (j & (H_FEATS - 1))];
    __nv_bfloat16 hi = __float2bfloat16(v);
    __nv_bfloat16 lo = __float2bfloat16(v - __bfloat162float(hi));
    g_Wbh[(size_t)j * H_FEATS + k] = hi;
    g_Wbl[(size_t)j * H_FEATS + k] = lo;
}

// ---------------------------------------------------------------------------
// Node GEMM on tensor cores (mma.sync bf16x3).
// C[50000 x 1024] = h @ [W1a | W1b]; tile 128x128, BK=64, 2-stage cp.async.
// Grid (8, 391), 256 threads (8 warps, 2x4: warp tile 64x32).
// ---------------------------------------------------------------------------
#define OFF_AH 0
#define OFF_AL 16384
#define OFF_BH 32768
#define OFF_BL 49152
#define STAGE  65536
#define GEMM_SMEM (2 * STAGE)
#define NKC (H_FEATS / 64)   // 8 k-chunks

__global__ __launch_bounds__(256, 1) void node_gemm_mma(const float* __restrict__ b1) {
    extern __shared__ char smem[];
    const unsigned sb = smem_u32(smem);
    const int tid = threadIdx.x, lane = tid & 31, wid = tid >> 5;
    const int bx = blockIdx.x, by = blockIdx.y;
    const int mBase = by * 128, nBase = bx * 128;
    const int mMax = N_NODES - mBase;
    const int wm = wid & 1;   // 0..1 -> m offset 0/64
    const int wn = wid >> 1;  // 0..3 -> n offset 0/32/64/96

    float acc[4][4][4];
    #pragma unroll
    for (int i = 0; i < 4; i++)
        #pragma unroll
        for (int j = 0; j < 4; j++)
            #pragma unroll
            for (int q = 0; q < 4; q++) acc[i][j][q] = 0.f;

    // ---- stage loader: 4 tiles of 128 rows x 128B, SW128 swizzled ----
    auto load_stage = [&](int kc, unsigned su) {
        const int k0 = kc * 64;
        #pragma unroll
        for (int i = 0; i < 4; i++) {
            int c = tid + 256 * i;          // 16B chunk id 0..1023
            int row = c >> 3;
            int cb = (c & 7) * 16;
            unsigned sw = SW128(row * 128 + cb);
            int feat = k0 + (cb >> 1);
            unsigned avs = (row < mMax) ? 16u : 0u;
            size_t aoff = (size_t)(mBase + ((row < mMax) ? row : 0)) * H_FEATS + feat;
            cp16(su + OFF_AH + sw, g_hh + aoff, avs);
            cp16(su + OFF_AL + sw, g_hl + aoff, avs);
            size_t boff = (size_t)(nBase + row) * H_FEATS + feat;
            cp16(su + OFF_BH + sw, g_Wbh + boff, 16u);
            cp16(su + OFF_BL + sw, g_Wbl + boff, 16u);
        }
        asm volatile("cp.async.commit_group;" ::: "memory");
    };

    load_stage(0, sb);
    load_stage(1, sb + STAGE);

    for (int kc = 0; kc < NKC; kc++) {
        // wait for stage kc (keep at most 1 younger group in flight)
        if (kc < NKC - 1)
            asm volatile("cp.async.wait_group 1;" ::: "memory");
        else
            asm volatile("cp.async.wait_group 0;" ::: "memory");
        __syncthreads();

        const unsigned su = sb + (kc & 1) * STAGE;

        #pragma unroll
        for (int s = 0; s < 4; s++) {   // 4 k16 steps within BK=64
            unsigned ah[4][4], al[4][4];
            #pragma unroll
            for (int mi = 0; mi < 4; mi++) {
                int row = wm * 64 + mi * 16 + (lane & 15);
                int cb = s * 32 + ((lane >> 4) << 4);
                unsigned sw = SW128(row * 128 + cb);
                ldsm4(ah[mi][0], ah[mi][1], ah[mi][2], ah[mi][3], su + OFF_AH + sw);
                ldsm4(al[mi][0], al[mi][1], al[mi][2], al[mi][3], su + OFF_AL + sw);
            }
            unsigned bh[4][2], bl[4][2];
            #pragma unroll
            for (int p = 0; p < 2; p++) {   // n-tile pairs (2p, 2p+1)
                int row = wn * 32 + p * 16 + (lane & 7) + ((lane >> 4) << 3);
                int cb = s * 32 + (((lane >> 3) & 1) << 4);
                unsigned sw = SW128(row * 128 + cb);
                unsigned r0, r1, r2, r3;
                ldsm4(r0, r1, r2, r3, su + OFF_BH + sw);
                bh[2 * p][0] = r0; bh[2 * p][1] = r1;
                bh[2 * p + 1][0] = r2; bh[2 * p + 1][1] = r3;
                ldsm4(r0, r1, r2, r3, su + OFF_BL + sw);
                bl[2 * p][0] = r0; bl[2 * p][1] = r1;
                bl[2 * p + 1][0] = r2; bl[2 * p + 1][1] = r3;
            }
            #pragma unroll
            for (int mi = 0; mi < 4; mi++)
                #pragma unroll
                for (int nj = 0; nj < 4; nj++) {
                    mma16816(acc[mi][nj], ah[mi], bh[nj]);   // hi*hi
                    mma16816(acc[mi][nj], ah[mi], bl[nj]);   // hi*lo
                    mma16816(acc[mi][nj], al[mi], bh[nj]);   // lo*hi
                }
        }
        __syncthreads();
        if (kc + 2 < NKC) load_stage(kc + 2, sb + (kc & 1) * STAGE);
    }

    // ---- epilogue ----
    const bool isA = (bx < 4);
    #pragma unroll
    for (int mi = 0; mi < 4; mi++) {
        #pragma unroll
        for (int half = 0; half < 2; half++) {
            int row = mBase + wm * 64 + mi * 16 + (lane >> 2) + half * 8;
            if (row >= N_NODES) continue;
            #pragma unroll
            for (int nj = 0; nj < 4; nj++) {
                int col = nBase + wn * 32 + nj * 8 + 2 * (lane & 3);
                float2 v;
                v.x = acc[mi][nj][2 * half];
                v.y = acc[mi][nj][2 * half + 1];
                if (isA) {
                    v.x += __ldg(b1 + col);
                    v.y += __ldg(b1 + col + 1);
                    *(float2*)(g_A + (size_t)row * H_FEATS + col) = v;
                } else {
                    *(float2*)(g_B + (size_t)row * H_FEATS + col - H_FEATS) = v;
                }
            }
        }
    }
}

// ---------------------------------------------------------------------------
// Edge kernel: one warp per edge.
// score[e] = sum_j relu(A[src][j] + B[dst][j]) * W2[j] + b2
// ---------------------------------------------------------------------------
__global__ __launch_bounds__(256) void edge_score(const int* __restrict__ src,
                                                  const int* __restrict__ dst,
                                                  const float* __restrict__ W2,
                                                  const float* __restrict__ b2,
                                                  float* __restrict__ out) {
    const int warpsPerBlock = blockDim.x >> 5;
    const int e = blockIdx.x * warpsPerBlock + (threadIdx.x >> 5);
    if (e >= N_EDGES) return;
    const int lane = threadIdx.x & 31;

    const int s = src[e];
    const int d = dst[e];

    const float4* a = (const float4*)(g_A + (size_t)s * H_FEATS);
    const float4* b = (const float4*)(g_B + (size_t)d * H_FEATS);
    const float4* w = (const float4*)W2;

    float sum = 0.f;
    #pragma unroll
    for (int c = 0; c < 4; c++) {
        int idx = c * 32 + lane;
        float4 av = a[idx];
        float4 bv = b[idx];
        float4 wv = w[idx];
        sum = fmaf(fmaxf(av.x + bv.x, 0.f), wv.x, sum);
        sum = fmaf(fmaxf(av.y + bv.y, 0.f), wv.y, sum);
        sum = fmaf(fmaxf(av.z + bv.z, 0.f), wv.z, sum);
        sum = fmaf(fmaxf(av.w + bv.w, 0.f), wv.w, sum);
    }
    #pragma unroll
    for (int off = 16; off > 0; off >>= 1)
        sum += __shfl_xor_sync(0xFFFFFFFFu, sum, off);

    if (lane == 0) out[e] = sum + b2[0];
}

// ---------------------------------------------------------------------------
// Launch
// ---------------------------------------------------------------------------
extern "C" void kernel_launch(void* const* d_in, const int* in_sizes, int n_in,
                              void* d_out, int out_size) {
    const float* h   = (const float*)d_in[0];
    const int*   src = (const int*)  d_in[1];
    const int*   dst = (const int*)  d_in[2];
    const float* W1  = (const float*)d_in[3];
    const float* b1  = (const float*)d_in[4];
    const float* W2  = (const float*)d_in[5];
    const float* b2  = (const float*)d_in[6];
    float* out = (float*)d_out;

    cudaFuncSetAttribute(node_gemm_mma, cudaFuncAttributeMaxDynamicSharedMemorySize, GEMM_SMEM);

    {   // h -> bf16 hi/lo
        int total = N_NODES * H_FEATS / 4;
        convert_h<<<(total + 255) / 256, 256>>>(h);
    }
    {   // W1 -> B-operand bf16 hi/lo
        int total = 1024 * H_FEATS;
        repack_w<<<(total + 255) / 256, 256>>>(W1);
    }
    {   // tensor-core GEMM
        dim3 grid(8, (N_NODES + 127) / 128);   // (8, 391)
        node_gemm_mma<<<grid, 256, GEMM_SMEM>>>(b1);
    }
    {   // edge scoring
        int warpsPerBlock = 8;
        int blocks = (N_EDGES + warpsPerBlock - 1) / warpsPerBlock;
        edge_score<<<blocks, 256>>>(src, dst, W2, b2, out);
    }
}